// round 1
// baseline (speedup 1.0000x reference)
#include <cuda_runtime.h>
#include <math.h>

#define BB 4
#define SS 1024
#define DIM 1280
#define NH 16
#define HD 80
// SCALE = 80^-0.5
#define SCALE 0.11180339887498948f

// Scratch (allocation-free rule: __device__ globals)
__device__ float g_qkv[(size_t)BB * SS * 3 * DIM];   // [B,S,3,H,HD] flattened
__device__ float g_attn[(size_t)BB * SS * DIM];      // [B,S,H*HD]

// ---------------------------------------------------------------------------
// Tiled fp32 GEMM with bias: C[M,N] = A[M,K] @ W[K,N] + bias[N]
// BM=128, BN=128, BK=16, 256 threads, 8x8 microtile.
// All dims divisible (M=4096, N in {3840,1280}, K=1280).
// ---------------------------------------------------------------------------
__global__ __launch_bounds__(256) void gemm_bias_kernel(
    const float* __restrict__ A, const float* __restrict__ W,
    const float* __restrict__ bias, float* __restrict__ C,
    int M, int N, int K)
{
    const int BM = 128, BN = 128, BK = 16;
    __shared__ float As[BK][BM];   // transposed A tile
    __shared__ float Bs[BK][BN];

    const int tid = threadIdx.x;
    const int tx = tid & 15;        // 0..15 -> column group
    const int ty = tid >> 4;        // 0..15 -> row group
    const int row0 = blockIdx.y * BM;
    const int col0 = blockIdx.x * BN;

    float acc[8][8];
    #pragma unroll
    for (int i = 0; i < 8; i++)
        #pragma unroll
        for (int j = 0; j < 8; j++) acc[i][j] = 0.0f;

    for (int k0 = 0; k0 < K; k0 += BK) {
        // Load A tile: 128x16 = 512 float4, 2 per thread
        #pragma unroll
        for (int t = tid; t < BM * BK / 4; t += 256) {
            int r  = t >> 2;          // BK/4 = 4 float4 per row
            int c4 = t & 3;
            float4 v = *(const float4*)&A[(size_t)(row0 + r) * K + k0 + c4 * 4];
            As[c4 * 4 + 0][r] = v.x;
            As[c4 * 4 + 1][r] = v.y;
            As[c4 * 4 + 2][r] = v.z;
            As[c4 * 4 + 3][r] = v.w;
        }
        // Load W tile: 16x128 = 512 float4, 2 per thread
        #pragma unroll
        for (int t = tid; t < BK * BN / 4; t += 256) {
            int r  = t >> 5;          // BN/4 = 32 float4 per row
            int c4 = t & 31;
            *(float4*)&Bs[r][c4 * 4] =
                *(const float4*)&W[(size_t)(k0 + r) * N + col0 + c4 * 4];
        }
        __syncthreads();

        #pragma unroll
        for (int kk = 0; kk < BK; kk++) {
            float a[8], b[8];
            #pragma unroll
            for (int i = 0; i < 8; i += 4) {
                float4 v = *(const float4*)&As[kk][ty * 8 + i];
                a[i] = v.x; a[i+1] = v.y; a[i+2] = v.z; a[i+3] = v.w;
            }
            #pragma unroll
            for (int j = 0; j < 8; j += 4) {
                float4 v = *(const float4*)&Bs[kk][tx * 8 + j];
                b[j] = v.x; b[j+1] = v.y; b[j+2] = v.z; b[j+3] = v.w;
            }
            #pragma unroll
            for (int i = 0; i < 8; i++)
                #pragma unroll
                for (int j = 0; j < 8; j++)
                    acc[i][j] += a[i] * b[j];
        }
        __syncthreads();
    }

    #pragma unroll
    for (int i = 0; i < 8; i++) {
        size_t r = row0 + ty * 8 + i;
        #pragma unroll
        for (int j = 0; j < 8; j++) {
            int c = col0 + tx * 8 + j;
            C[r * N + c] = acc[i][j] + bias[c];
        }
    }
}

// ---------------------------------------------------------------------------
// RoPE in-place on q,k inside g_qkv ([B,S,3,H,HD], c=0 -> q, c=1 -> k)
// one thread per rotation pair (d, d+40)
// ---------------------------------------------------------------------------
__global__ void rope_kernel(float* __restrict__ qkv,
                            const float* __restrict__ cosT,
                            const float* __restrict__ sinT)
{
    const int HALF = HD / 2;  // 40
    int idx = blockIdx.x * blockDim.x + threadIdx.x;
    const int total = BB * SS * 2 * NH * HALF;
    if (idx >= total) return;
    int d  = idx % HALF;
    int h  = (idx / HALF) % NH;
    int c  = (idx / (HALF * NH)) % 2;
    int bs = idx / (HALF * NH * 2);
    int s  = bs % SS;

    float* base = qkv + (size_t)bs * 3 * DIM + c * DIM + h * HD;
    float x1 = base[d];
    float x2 = base[d + HALF];
    // emb = concat(freqs,freqs): cos[s][d] == cos[s][d+HALF]
    float cs = cosT[s * HD + d];
    float sn = sinT[s * HD + d];
    base[d]        = x1 * cs - x2 * sn;
    base[d + HALF] = x2 * cs + x1 * sn;
}

// ---------------------------------------------------------------------------
// Flash attention (fp32, online softmax).
// grid = (S/64, B*H), block = 256 threads (8 warps).
// Each block handles 64 query rows of one (b,h). Warp w owns rows w*8..w*8+7.
// Lane owns key columns {lane, lane+32} for scores and output columns
// {lane, lane+32, lane+64(if lane<16)} for the O accumulator.
// Dynamic smem: Qs[64][81] Ks[64][81] Vs[64][81] Ps[8][8][64]
// ---------------------------------------------------------------------------
__global__ __launch_bounds__(256) void flash_kernel(
    const float* __restrict__ qkv, float* __restrict__ out)
{
    extern __shared__ float smem[];
    float (*Qs)[81] = (float (*)[81])smem;
    float (*Ks)[81] = (float (*)[81])(smem + 64 * 81);
    float (*Vs)[81] = (float (*)[81])(smem + 2 * 64 * 81);
    float (*Ps)[64] = (float (*)[64])(smem + 3 * 64 * 81);  // [8 warps * 8 rows][64]

    const int bh = blockIdx.y;
    const int b = bh / NH, h = bh % NH;
    const int q0 = blockIdx.x * 64;
    const int tid = threadIdx.x;
    const int w = tid >> 5, lane = tid & 31;

    // Load Q tile (RoPE already applied)
    for (int t = tid; t < 64 * HD; t += 256) {
        int r = t / HD, d = t % HD;
        Qs[r][d] = qkv[(size_t)(b * SS + q0 + r) * 3 * DIM + h * HD + d];
    }

    float m[8], l[8], o0[8], o1[8], o2[8];
    #pragma unroll
    for (int i = 0; i < 8; i++) {
        m[i] = -1e30f; l[i] = 0.0f;
        o0[i] = o1[i] = o2[i] = 0.0f;
    }
    __syncthreads();

    for (int kt = 0; kt < SS; kt += 64) {
        // Load K,V tiles
        for (int t = tid; t < 64 * HD; t += 256) {
            int r = t / HD, d = t % HD;
            size_t base = (size_t)(b * SS + kt + r) * 3 * DIM + h * HD + d;
            Ks[r][d] = qkv[base + DIM];
            Vs[r][d] = qkv[base + 2 * DIM];
        }
        __syncthreads();

        // Scores: rows in chunks of 4 to amortize K loads
        float s0[8], s1[8];
        #pragma unroll
        for (int ii = 0; ii < 8; ii += 4) {
            float a0[4] = {0, 0, 0, 0}, a1[4] = {0, 0, 0, 0};
            #pragma unroll 4
            for (int d = 0; d < HD; d++) {
                float k0 = Ks[lane][d];
                float k1 = Ks[lane + 32][d];
                #pragma unroll
                for (int i2 = 0; i2 < 4; i2++) {
                    float qv = Qs[w * 8 + ii + i2][d];
                    a0[i2] += qv * k0;
                    a1[i2] += qv * k1;
                }
            }
            #pragma unroll
            for (int i2 = 0; i2 < 4; i2++) {
                s0[ii + i2] = a0[i2] * SCALE;
                s1[ii + i2] = a1[i2] * SCALE;
            }
        }

        // Online softmax per row + stash P to smem
        #pragma unroll
        for (int i = 0; i < 8; i++) {
            float mt = fmaxf(s0[i], s1[i]);
            #pragma unroll
            for (int off = 16; off > 0; off >>= 1)
                mt = fmaxf(mt, __shfl_xor_sync(0xffffffffu, mt, off));
            float mnew  = fmaxf(m[i], mt);
            float alpha = __expf(m[i] - mnew);
            float p0 = __expf(s0[i] - mnew);
            float p1 = __expf(s1[i] - mnew);
            float ps = p0 + p1;
            #pragma unroll
            for (int off = 16; off > 0; off >>= 1)
                ps += __shfl_xor_sync(0xffffffffu, ps, off);
            l[i] = l[i] * alpha + ps;
            m[i] = mnew;
            o0[i] *= alpha; o1[i] *= alpha; o2[i] *= alpha;
            Ps[w * 8 + i][lane]      = p0;
            Ps[w * 8 + i][lane + 32] = p1;
        }
        __syncwarp();

        // O += P @ V
        #pragma unroll
        for (int i = 0; i < 8; i++) {
            #pragma unroll 4
            for (int j = 0; j < 64; j++) {
                float pv = Ps[w * 8 + i][j];
                o0[i] += pv * Vs[j][lane];
                o1[i] += pv * Vs[j][lane + 32];
                if (lane < 16) o2[i] += pv * Vs[j][lane + 64];
            }
        }
        __syncthreads();
    }

    // Normalize + write [B,S,H*HD]
    #pragma unroll
    for (int i = 0; i < 8; i++) {
        int q = q0 + w * 8 + i;
        float inv = 1.0f / l[i];
        size_t base = (size_t)(b * SS + q) * DIM + h * HD;
        out[base + lane]      = o0[i] * inv;
        out[base + lane + 32] = o1[i] * inv;
        if (lane < 16) out[base + lane + 64] = o2[i] * inv;
    }
}

// ---------------------------------------------------------------------------
// Launch
// ---------------------------------------------------------------------------
extern "C" void kernel_launch(void* const* d_in, const int* in_sizes, int n_in,
                              void* d_out, int out_size)
{
    const float* x        = (const float*)d_in[0];
    const float* rope_cos = (const float*)d_in[1];
    const float* rope_sin = (const float*)d_in[2];
    const float* Wqkv     = (const float*)d_in[3];
    const float* bqkv     = (const float*)d_in[4];
    const float* Wproj    = (const float*)d_in[5];
    const float* bproj    = (const float*)d_in[6];
    float* out = (float*)d_out;

    float* qkv  = nullptr;
    float* attn = nullptr;
    cudaGetSymbolAddress((void**)&qkv,  g_qkv);
    cudaGetSymbolAddress((void**)&attn, g_attn);

    const int M = BB * SS;  // 4096

    // 1) QKV GEMM + bias
    {
        dim3 grid(3 * DIM / 128, M / 128);   // (30, 32)
        gemm_bias_kernel<<<grid, 256>>>(x, Wqkv, bqkv, qkv, M, 3 * DIM, DIM);
    }

    // 2) RoPE on q,k
    {
        int total = BB * SS * 2 * NH * (HD / 2);
        rope_kernel<<<(total + 255) / 256, 256>>>(qkv, rope_cos, rope_sin);
    }

    // 3) Flash attention
    {
        int smem_bytes = (3 * 64 * 81 + 8 * 8 * 64) * sizeof(float);  // 78592
        cudaFuncSetAttribute(flash_kernel,
                             cudaFuncAttributeMaxDynamicSharedMemorySize,
                             smem_bytes);
        dim3 grid(SS / 64, BB * NH);          // (16, 64)
        flash_kernel<<<grid, 256, smem_bytes>>>(qkv, attn);
    }

    // 4) Output projection + bias
    {
        dim3 grid(DIM / 128, M / 128);        // (10, 32)
        gemm_bias_kernel<<<grid, 256>>>(attn, Wproj, bproj, out, M, DIM, DIM);
    }
}

// round 2
// speedup vs baseline: 1.2985x; 1.2985x over previous
#include <cuda_runtime.h>
#include <math.h>

#define BB 4
#define SS 1024
#define DIM 1280
#define NH 16
#define HD 80
#define SCALE 0.11180339887498948f

// Scratch (allocation-free rule: __device__ globals)
__device__ float g_qkv[(size_t)BB * SS * 3 * DIM];   // [B,S,3,H,HD] flattened
__device__ float g_attn[(size_t)BB * SS * DIM];      // [B,S,H*HD]

// ---------------------------------------------------------------------------
// Tiled fp32 GEMM with bias: C[M,N] = A[M,K] @ W[K,N] + bias[N]
// BM=128, BN=128, BK=16, 256 threads, 8x8 microtile.
// ---------------------------------------------------------------------------
__global__ __launch_bounds__(256) void gemm_bias_kernel(
    const float* __restrict__ A, const float* __restrict__ W,
    const float* __restrict__ bias, float* __restrict__ C,
    int M, int N, int K)
{
    const int BM = 128, BN = 128, BK = 16;
    __shared__ float As[BK][BM];   // transposed A tile
    __shared__ float Bs[BK][BN];

    const int tid = threadIdx.x;
    const int tx = tid & 15;
    const int ty = tid >> 4;
    const int row0 = blockIdx.y * BM;
    const int col0 = blockIdx.x * BN;

    float acc[8][8];
    #pragma unroll
    for (int i = 0; i < 8; i++)
        #pragma unroll
        for (int j = 0; j < 8; j++) acc[i][j] = 0.0f;

    for (int k0 = 0; k0 < K; k0 += BK) {
        #pragma unroll
        for (int t = tid; t < BM * BK / 4; t += 256) {
            int r  = t >> 2;
            int c4 = t & 3;
            float4 v = *(const float4*)&A[(size_t)(row0 + r) * K + k0 + c4 * 4];
            As[c4 * 4 + 0][r] = v.x;
            As[c4 * 4 + 1][r] = v.y;
            As[c4 * 4 + 2][r] = v.z;
            As[c4 * 4 + 3][r] = v.w;
        }
        #pragma unroll
        for (int t = tid; t < BK * BN / 4; t += 256) {
            int r  = t >> 5;
            int c4 = t & 31;
            *(float4*)&Bs[r][c4 * 4] =
                *(const float4*)&W[(size_t)(k0 + r) * N + col0 + c4 * 4];
        }
        __syncthreads();

        #pragma unroll
        for (int kk = 0; kk < BK; kk++) {
            float a[8], b[8];
            #pragma unroll
            for (int i = 0; i < 8; i += 4) {
                float4 v = *(const float4*)&As[kk][ty * 8 + i];
                a[i] = v.x; a[i+1] = v.y; a[i+2] = v.z; a[i+3] = v.w;
            }
            #pragma unroll
            for (int j = 0; j < 8; j += 4) {
                float4 v = *(const float4*)&Bs[kk][tx * 8 + j];
                b[j] = v.x; b[j+1] = v.y; b[j+2] = v.z; b[j+3] = v.w;
            }
            #pragma unroll
            for (int i = 0; i < 8; i++)
                #pragma unroll
                for (int j = 0; j < 8; j++)
                    acc[i][j] += a[i] * b[j];
        }
        __syncthreads();
    }

    #pragma unroll
    for (int i = 0; i < 8; i++) {
        size_t r = row0 + ty * 8 + i;
        #pragma unroll
        for (int j = 0; j < 8; j++) {
            int c = col0 + tx * 8 + j;
            C[r * N + c] = acc[i][j] + bias[c];
        }
    }
}

// ---------------------------------------------------------------------------
// RoPE in-place on q,k inside g_qkv
// ---------------------------------------------------------------------------
__global__ void rope_kernel(float* __restrict__ qkv,
                            const float* __restrict__ cosT,
                            const float* __restrict__ sinT)
{
    const int HALF = HD / 2;  // 40
    int idx = blockIdx.x * blockDim.x + threadIdx.x;
    const int total = BB * SS * 2 * NH * HALF;
    if (idx >= total) return;
    int d  = idx % HALF;
    int h  = (idx / HALF) % NH;
    int c  = (idx / (HALF * NH)) % 2;
    int bs = idx / (HALF * NH * 2);
    int s  = bs % SS;

    float* base = qkv + (size_t)bs * 3 * DIM + c * DIM + h * HD;
    float x1 = base[d];
    float x2 = base[d + HALF];
    float cs = cosT[s * HD + d];
    float sn = sinT[s * HD + d];
    base[d]        = x1 * cs - x2 * sn;
    base[d + HALF] = x2 * cs + x1 * sn;
}

// ---------------------------------------------------------------------------
// Flash attention v2: register-blocked GEMM structure.
// grid = (S/128, B*H), block = 256 threads.
// Q tile = 128 rows, K/V tile = 64 rows.
// Thread grid 16x16: ty = tid/16 owns query rows ty*8..ty*8+7 (both phases),
// tx owns score cols tx*4..+3 (phase 1) and output dims {tx+16*jj} (phase 2).
//
// smem (dynamic):
//   Qt[80][132]  (Q transposed, 132-stride for STS/LDS alignment)
//   Kt[80][68]   (K transposed)
//   Vs[64][80]   (V natural)
//   Pt[64][132]  (probabilities, transposed: Pt[key][query])
// total = 29568 floats = 118272 bytes
// ---------------------------------------------------------------------------
__global__ __launch_bounds__(256) void flash_kernel(
    const float* __restrict__ qkv, float* __restrict__ out)
{
    extern __shared__ float smem[];
    float* Qt = smem;                 // [80][132]
    float* Kt = Qt + 80 * 132;        // [80][68]
    float* Vs = Kt + 80 * 68;         // [64][80]
    float* Pt = Vs + 64 * 80;         // [64][132]

    const int bh = blockIdx.y;
    const int b = bh / NH, h = bh % NH;
    const int q0 = blockIdx.x * 128;
    const int tid = threadIdx.x;
    const int ty = tid >> 4;   // 0..15: row group (8 rows)
    const int tx = tid & 15;   // 0..15: col group

    // Load Q tile transposed: Qt[d][r]
    for (int t = tid; t < 128 * 20; t += 256) {
        int r = t / 20, d4 = (t % 20) * 4;
        float4 v = *(const float4*)&qkv[(size_t)(b * SS + q0 + r) * 3 * DIM + h * HD + d4];
        Qt[(d4 + 0) * 132 + r] = v.x;
        Qt[(d4 + 1) * 132 + r] = v.y;
        Qt[(d4 + 2) * 132 + r] = v.z;
        Qt[(d4 + 3) * 132 + r] = v.w;
    }

    float m[8], l[8], o[8][5];
    #pragma unroll
    for (int i = 0; i < 8; i++) {
        m[i] = -1e30f; l[i] = 0.0f;
        #pragma unroll
        for (int jj = 0; jj < 5; jj++) o[i][jj] = 0.0f;
    }

    for (int kt = 0; kt < SS; kt += 64) {
        __syncthreads();   // previous tile fully consumed (Vs, Pt) + Q ready
        // Load K transposed + V natural
        for (int t = tid; t < 64 * 20; t += 256) {
            int r = t / 20, d4 = (t % 20) * 4;
            size_t base = (size_t)(b * SS + kt + r) * 3 * DIM + h * HD + d4;
            float4 kv = *(const float4*)&qkv[base + DIM];
            Kt[(d4 + 0) * 68 + r] = kv.x;
            Kt[(d4 + 1) * 68 + r] = kv.y;
            Kt[(d4 + 2) * 68 + r] = kv.z;
            Kt[(d4 + 3) * 68 + r] = kv.w;
            *(float4*)&Vs[r * 80 + d4] = *(const float4*)&qkv[base + 2 * DIM];
        }
        __syncthreads();

        // ---- Phase 1: scores S = Q @ K^T (8x4 microtile) ----
        float acc[8][4];
        #pragma unroll
        for (int i = 0; i < 8; i++)
            #pragma unroll
            for (int j = 0; j < 4; j++) acc[i][j] = 0.0f;

        #pragma unroll 4
        for (int k = 0; k < HD; k++) {
            float4 a0 = *(const float4*)&Qt[k * 132 + ty * 8];
            float4 a1 = *(const float4*)&Qt[k * 132 + ty * 8 + 4];
            float4 bq = *(const float4*)&Kt[k * 68 + tx * 4];
            float a[8] = {a0.x, a0.y, a0.z, a0.w, a1.x, a1.y, a1.z, a1.w};
            float bv[4] = {bq.x, bq.y, bq.z, bq.w};
            #pragma unroll
            for (int i = 0; i < 8; i++)
                #pragma unroll
                for (int j = 0; j < 4; j++)
                    acc[i][j] += a[i] * bv[j];
        }

        // ---- Online softmax (rows owned by 16-lane tx-groups) ----
        #pragma unroll
        for (int i = 0; i < 8; i++) {
            #pragma unroll
            for (int j = 0; j < 4; j++) acc[i][j] *= SCALE;
            float mt = fmaxf(fmaxf(acc[i][0], acc[i][1]),
                             fmaxf(acc[i][2], acc[i][3]));
            #pragma unroll
            for (int off = 8; off > 0; off >>= 1)
                mt = fmaxf(mt, __shfl_xor_sync(0xffffffffu, mt, off));
            float mnew  = fmaxf(m[i], mt);
            float alpha = __expf(m[i] - mnew);
            float ps = 0.0f;
            #pragma unroll
            for (int j = 0; j < 4; j++) {
                acc[i][j] = __expf(acc[i][j] - mnew);
                ps += acc[i][j];
            }
            #pragma unroll
            for (int off = 8; off > 0; off >>= 1)
                ps += __shfl_xor_sync(0xffffffffu, ps, off);
            l[i] = l[i] * alpha + ps;
            m[i] = mnew;
            #pragma unroll
            for (int jj = 0; jj < 5; jj++) o[i][jj] *= alpha;
        }

        // Stash P transposed: Pt[key][query]
        #pragma unroll
        for (int j2 = 0; j2 < 4; j2++) {
            float4 lo = make_float4(acc[0][j2], acc[1][j2], acc[2][j2], acc[3][j2]);
            float4 hi = make_float4(acc[4][j2], acc[5][j2], acc[6][j2], acc[7][j2]);
            *(float4*)&Pt[(tx * 4 + j2) * 132 + ty * 8]     = lo;
            *(float4*)&Pt[(tx * 4 + j2) * 132 + ty * 8 + 4] = hi;
        }
        __syncthreads();

        // ---- Phase 2: O += P @ V (8x5 microtile) ----
        #pragma unroll 2
        for (int j = 0; j < 64; j++) {
            float4 pa = *(const float4*)&Pt[j * 132 + ty * 8];
            float4 pb = *(const float4*)&Pt[j * 132 + ty * 8 + 4];
            float p[8] = {pa.x, pa.y, pa.z, pa.w, pb.x, pb.y, pb.z, pb.w};
            float v[5];
            #pragma unroll
            for (int jj = 0; jj < 5; jj++) v[jj] = Vs[j * 80 + tx + 16 * jj];
            #pragma unroll
            for (int i = 0; i < 8; i++)
                #pragma unroll
                for (int jj = 0; jj < 5; jj++)
                    o[i][jj] += p[i] * v[jj];
        }
    }

    // Normalize + write [B,S,H*HD]
    #pragma unroll
    for (int i = 0; i < 8; i++) {
        float inv = 1.0f / l[i];
        size_t base = (size_t)(b * SS + q0 + ty * 8 + i) * DIM + h * HD;
        #pragma unroll
        for (int jj = 0; jj < 5; jj++)
            out[base + tx + 16 * jj] = o[i][jj] * inv;
    }
}

// ---------------------------------------------------------------------------
// Launch
// ---------------------------------------------------------------------------
extern "C" void kernel_launch(void* const* d_in, const int* in_sizes, int n_in,
                              void* d_out, int out_size)
{
    const float* x        = (const float*)d_in[0];
    const float* rope_cos = (const float*)d_in[1];
    const float* rope_sin = (const float*)d_in[2];
    const float* Wqkv     = (const float*)d_in[3];
    const float* bqkv     = (const float*)d_in[4];
    const float* Wproj    = (const float*)d_in[5];
    const float* bproj    = (const float*)d_in[6];
    float* out = (float*)d_out;

    float* qkv  = nullptr;
    float* attn = nullptr;
    cudaGetSymbolAddress((void**)&qkv,  g_qkv);
    cudaGetSymbolAddress((void**)&attn, g_attn);

    const int M = BB * SS;  // 4096

    // 1) QKV GEMM + bias
    {
        dim3 grid(3 * DIM / 128, M / 128);   // (30, 32)
        gemm_bias_kernel<<<grid, 256>>>(x, Wqkv, bqkv, qkv, M, 3 * DIM, DIM);
    }

    // 2) RoPE on q,k
    {
        int total = BB * SS * 2 * NH * (HD / 2);
        rope_kernel<<<(total + 255) / 256, 256>>>(qkv, rope_cos, rope_sin);
    }

    // 3) Flash attention
    {
        int smem_bytes = (80 * 132 + 80 * 68 + 64 * 80 + 64 * 132) * sizeof(float);
        cudaFuncSetAttribute(flash_kernel,
                             cudaFuncAttributeMaxDynamicSharedMemorySize,
                             smem_bytes);
        dim3 grid(SS / 128, BB * NH);         // (8, 64)
        flash_kernel<<<grid, 256, smem_bytes>>>(qkv, attn);
    }

    // 4) Output projection + bias
    {
        dim3 grid(DIM / 128, M / 128);        // (10, 32)
        gemm_bias_kernel<<<grid, 256>>>(attn, Wproj, bproj, out, M, DIM, DIM);
    }
}